// round 9
// baseline (speedup 1.0000x reference)
#include <cuda_runtime.h>
#include <cstdint>

#define MAXN 100000
typedef unsigned long long ull;

// ---------------- device scratch (static: no allocations allowed) ----------------
__device__ float  g_bn[8];              // sum[4], sumsq[4]
__device__ float  g_deg[MAXN];
__device__ float4 g_enc_acc[MAXN];      // {mu0,mu1,lv0,lv1} sums
__device__ float4 g_dec_acc[MAXN];      // {o0..o3} sums
__device__ float4 g_ea[MAXN * 8];       // A@xn + b1  (N x 32)
__device__ float4 g_eb[MAXN * 8];       // B@xn       (N x 32)
__device__ float4 g_da[MAXN * 8];       // decoder A@z + b1
__device__ float4 g_db[MAXN * 8];       // decoder B@z

__device__ __forceinline__ void red_add_v4(float* p, float a, float b, float c, float d) {
    asm volatile("red.global.add.v4.f32 [%0], {%1,%2,%3,%4};"
                 :: "l"(p), "f"(a), "f"(b), "f"(c), "f"(d) : "memory");
}
__device__ __forceinline__ void red_add_f32(float* p, float a) {
    asm volatile("red.global.add.f32 [%0], %1;" :: "l"(p), "f"(a) : "memory");
}
__device__ __forceinline__ ull pack2(float lo, float hi) {
    ull d;
    asm("mov.b64 %0, {%1, %2};" : "=l"(d) : "f"(lo), "f"(hi));
    return d;
}
__device__ __forceinline__ ull packdup(float x) {
    ull d;
    asm("mov.b64 %0, {%1, %1};" : "=l"(d) : "f"(x));
    return d;
}
__device__ __forceinline__ void unpack2(ull v, float& lo, float& hi) {
    asm("mov.b64 {%0, %1}, %2;" : "=f"(lo), "=f"(hi) : "l"(v));
}
__device__ __forceinline__ ull fma2(ull a, ull b, ull c) {
    ull d;
    asm("fma.rn.f32x2 %0, %1, %2, %3;" : "=l"(d) : "l"(a), "l"(b), "l"(c));
    return d;
}
// pack two f32 to f16x2: hi -> high half, lo -> low half
__device__ __forceinline__ uint32_t cvt_h2(float hi, float lo) {
    uint32_t r;
    asm("cvt.rn.f16x2.f32 %0, %1, %2;" : "=r"(r) : "f"(hi), "f"(lo));
    return r;
}

// ---------------- zero accumulators ----------------
__global__ void k_zero(int n) {
    int t = blockIdx.x * blockDim.x + threadIdx.x;
    int stride = gridDim.x * blockDim.x;
    float4 z = make_float4(0.f, 0.f, 0.f, 0.f);
    for (int i = t; i < n; i += stride) {
        g_enc_acc[i] = z;
        g_dec_acc[i] = z;
        g_deg[i] = 0.f;
    }
    if (t < 8) g_bn[t] = 0.f;
}

// ---------------- batchnorm statistics ----------------
__global__ void k_bn_reduce(const float4* __restrict__ x, int n) {
    int t = blockIdx.x * blockDim.x + threadIdx.x;
    int stride = gridDim.x * blockDim.x;
    float s[4] = {0.f, 0.f, 0.f, 0.f};
    float q[4] = {0.f, 0.f, 0.f, 0.f};
    for (int i = t; i < n; i += stride) {
        float4 v = x[i];
        s[0] += v.x; q[0] += v.x * v.x;
        s[1] += v.y; q[1] += v.y * v.y;
        s[2] += v.z; q[2] += v.z * v.z;
        s[3] += v.w; q[3] += v.w * v.w;
    }
#pragma unroll
    for (int o = 16; o > 0; o >>= 1) {
#pragma unroll
        for (int c = 0; c < 4; c++) {
            s[c] += __shfl_down_sync(0xffffffffu, s[c], o);
            q[c] += __shfl_down_sync(0xffffffffu, q[c], o);
        }
    }
    if ((threadIdx.x & 31) == 0) {
#pragma unroll
        for (int c = 0; c < 4; c++) {
            atomicAdd(&g_bn[c], s[c]);
            atomicAdd(&g_bn[4 + c], q[c]);
        }
    }
}

// ---------------- encoder node precompute: BN + linearized layer 1 ----------------
__global__ void k_prep_enc(const float4* __restrict__ x,
                           const float* __restrict__ w1, const float* __restrict__ b1,
                           const float* __restrict__ gamma, const float* __restrict__ beta,
                           int n) {
    __shared__ float sw[256];   // enc_w1 (32 x 8) row-major
    __shared__ float sb1[32];
    __shared__ float sm[4], ss[4], sbt[4];
    int tid = threadIdx.x;
    if (tid < 256) sw[tid] = w1[tid];
    if (tid < 32)  sb1[tid] = b1[tid];
    if (tid < 4) {
        float m = g_bn[tid] / (float)n;
        float var = g_bn[4 + tid] / (float)n - m * m;
        sm[tid]  = m;
        ss[tid]  = rsqrtf(var + 1e-5f) * gamma[tid];
        sbt[tid] = beta[tid];
    }
    __syncthreads();
    int t = blockIdx.x * blockDim.x + tid;
    int stride = gridDim.x * blockDim.x;
    for (int i = t; i < n; i += stride) {
        float4 xv = x[i];
        float x0 = (xv.x - sm[0]) * ss[0] + sbt[0];
        float x1 = (xv.y - sm[1]) * ss[1] + sbt[1];
        float x2 = (xv.z - sm[2]) * ss[2] + sbt[2];
        float x3 = (xv.w - sm[3]) * ss[3] + sbt[3];
        float4 ra[8], rb[8];
        float* pa = (float*)ra;
        float* pb = (float*)rb;
#pragma unroll
        for (int k = 0; k < 32; k++) {
            const float* w = sw + k * 8;
            float b = w[4] * x0 + w[5] * x1 + w[6] * x2 + w[7] * x3;
            float a = sb1[k] + w[0] * x0 + w[1] * x1 + w[2] * x2 + w[3] * x3 - b;
            pa[k] = a;
            pb[k] = b;
        }
#pragma unroll
        for (int q8 = 0; q8 < 8; q8++) {
            g_ea[i * 8 + q8] = ra[q8];
            g_eb[i * 8 + q8] = rb[q8];
        }
    }
}

// ---------------- per-edge kernel: staged fp16 gather -> mma.sync f16 -> project + RED ----
// Warp-tile = 32 edges (M=32). A = fp16 u rows [32x32] in warp-private smem stage
// (16-word rows, 4-word XOR block swizzle: blk ^= (row>>1)&3 -> conflict-free STS/LDS).
// B = W2 [32x32] fp16x2 persistent register fragments (16 regs). Bias seeds accumulators.
// Epilogue: relu, packed projection, shfl-reduce over tg, RED from tg==0.
template <int PHASE>
__global__ void __launch_bounds__(128, 6)
k_edge(const int* __restrict__ ei, int E, int n,
       const float* __restrict__ w2, const float* __restrict__ b2,
       const float* __restrict__ pA, const float* __restrict__ pB) {
    __shared__ uint32_t su[4 * 512];         // 4 warps x 32 rows x 16 words (8KB)
    __shared__ ull s_pc01[32], s_pc23[32];   // {pA[c],pA[32+c]}, {pB[c],pB[32+c]}
    __shared__ float s_b2[32];
    int tid = threadIdx.x;
    int warp = tid >> 5, lane = tid & 31;
    int g = lane >> 2, tg = lane & 3;

    if (tid < 32) {
        s_pc01[tid] = pack2(pA[tid], pA[32 + tid]);
        s_pc23[tid] = pack2(pB[tid], pB[32 + tid]);
        s_b2[tid] = b2[tid];
    }

    // Persistent B fragments (fp16x2): bf0/bf1[nt][kt], n = 8nt+g, k base = 16kt
    uint32_t bf0[4][2], bf1[4][2];
#pragma unroll
    for (int nt = 0; nt < 4; nt++)
#pragma unroll
        for (int kt = 0; kt < 2; kt++) {
            const float* wr = w2 + (8 * nt + g) * 32 + 16 * kt;
            bf0[nt][kt] = cvt_h2(wr[2 * tg + 1], wr[2 * tg]);
            bf1[nt][kt] = cvt_h2(wr[2 * tg + 9], wr[2 * tg + 8]);
        }
    __syncthreads();

    const float4* fa = (PHASE == 0) ? g_ea : g_da;
    const float4* fb = (PHASE == 0) ? g_eb : g_db;
    float* acc = (PHASE == 0) ? (float*)g_enc_acc : (float*)g_dec_acc;

    uint32_t* stage = su + warp * 512;
    int c4 = lane & 3, rsub = lane >> 2;   // gather: 4 lanes per row, 8 rows per pass
    int ntiles = (E + 127) >> 7;
    const ull ONE = packdup(1.0f);

    for (int t = blockIdx.x; t < ntiles; t += gridDim.x) {
        int e = (t << 7) + (warp << 5) + lane;
        bool ok = (e < E);
        int ec = ok ? e : (E - 1);
        unsigned j = (unsigned)ei[ec];
        unsigned i = (unsigned)ei[E + ec];
        ok = ok && (j < (unsigned)n) && (i < (unsigned)n);
        unsigned js = ok ? j : 0u, is = ok ? i : 0u;
        unsigned oki = ok ? 1u : 0u;

        __syncwarp();   // stage is warp-private; prior iter reads done
#pragma unroll
        for (int p = 0; p < 4; p++) {
            int er = p * 8 + rsub;
            unsigned nd = __shfl_sync(0xffffffffu, is, er);
            unsigned ns = __shfl_sync(0xffffffffu, js, er);
            const float4* pa = fa + nd * 8 + c4 * 2;
            const float4* pb = fb + ns * 8 + c4 * 2;
            float4 a0 = pa[0], a1 = pa[1];
            float4 b0 = pb[0], b1 = pb[1];
            uint4 w;
            w.x = cvt_h2(fmaxf(a0.y + b0.y, 0.f), fmaxf(a0.x + b0.x, 0.f));
            w.y = cvt_h2(fmaxf(a0.w + b0.w, 0.f), fmaxf(a0.z + b0.z, 0.f));
            w.z = cvt_h2(fmaxf(a1.y + b1.y, 0.f), fmaxf(a1.x + b1.x, 0.f));
            w.w = cvt_h2(fmaxf(a1.w + b1.w, 0.f), fmaxf(a1.z + b1.z, 0.f));
            int blk = c4 ^ ((er >> 1) & 3);
            *(uint4*)(stage + er * 16 + blk * 4) = w;
        }
        __syncwarp();

#pragma unroll
        for (int mt = 0; mt < 2; mt++) {
            float c[4][4];
#pragma unroll
            for (int nt = 0; nt < 4; nt++) {
                float bb0 = s_b2[8 * nt + 2 * tg];
                float bb1 = s_b2[8 * nt + 2 * tg + 1];
                c[nt][0] = bb0; c[nt][1] = bb1;
                c[nt][2] = bb0; c[nt][3] = bb1;
            }

            int r0 = mt * 16 + g, r1 = r0 + 8;
            int s0 = (r0 >> 1) & 3, s1 = (r1 >> 1) & 3;
#pragma unroll
            for (int kt = 0; kt < 2; kt++) {
                uint32_t a0 = stage[r0 * 16 + ((2 * kt) ^ s0) * 4 + tg];
                uint32_t a1 = stage[r1 * 16 + ((2 * kt) ^ s1) * 4 + tg];
                uint32_t a2 = stage[r0 * 16 + ((2 * kt + 1) ^ s0) * 4 + tg];
                uint32_t a3 = stage[r1 * 16 + ((2 * kt + 1) ^ s1) * 4 + tg];
#pragma unroll
                for (int nt = 0; nt < 4; nt++) {
                    asm volatile(
                        "mma.sync.aligned.m16n8k16.row.col.f32.f16.f16.f32 "
                        "{%0,%1,%2,%3}, {%4,%5,%6,%7}, {%8,%9}, {%0,%1,%2,%3};"
                        : "+f"(c[nt][0]), "+f"(c[nt][1]), "+f"(c[nt][2]), "+f"(c[nt][3])
                        : "r"(a0), "r"(a1), "r"(a2), "r"(a3),
                          "r"(bf0[nt][kt]), "r"(bf1[nt][kt]));
                }
            }

            // epilogue: rows r0 = mt*16+g, r1 = mt*16+8+g
            ull p01a = 0, p23a = 0, p01b = 0, p23b = 0;
#pragma unroll
            for (int nt = 0; nt < 4; nt++) {
                int c0i = 8 * nt + 2 * tg;
                ull q0 = s_pc01[c0i], q1 = s_pc01[c0i + 1];
                ull q2 = s_pc23[c0i], q3 = s_pc23[c0i + 1];
                float r0f = fmaxf(c[nt][0], 0.f);
                float r1f = fmaxf(c[nt][1], 0.f);
                float r2f = fmaxf(c[nt][2], 0.f);
                float r3f = fmaxf(c[nt][3], 0.f);
                p01a = fma2(q0, packdup(r0f), p01a);
                p23a = fma2(q2, packdup(r0f), p23a);
                p01a = fma2(q1, packdup(r1f), p01a);
                p23a = fma2(q3, packdup(r1f), p23a);
                p01b = fma2(q0, packdup(r2f), p01b);
                p23b = fma2(q2, packdup(r2f), p23b);
                p01b = fma2(q1, packdup(r3f), p01b);
                p23b = fma2(q3, packdup(r3f), p23b);
            }
            // reduce over tg (lanes xor 1, xor 2)
#pragma unroll
            for (int m = 1; m <= 2; m <<= 1) {
                p01a = fma2(ONE, __shfl_xor_sync(0xffffffffu, p01a, m), p01a);
                p23a = fma2(ONE, __shfl_xor_sync(0xffffffffu, p23a, m), p23a);
                p01b = fma2(ONE, __shfl_xor_sync(0xffffffffu, p01b, m), p01b);
                p23b = fma2(ONE, __shfl_xor_sync(0xffffffffu, p23b, m), p23b);
            }
            unsigned iR0  = __shfl_sync(0xffffffffu, is,  mt * 16 + g);
            unsigned okR0 = __shfl_sync(0xffffffffu, oki, mt * 16 + g);
            unsigned iR1  = __shfl_sync(0xffffffffu, is,  mt * 16 + 8 + g);
            unsigned okR1 = __shfl_sync(0xffffffffu, oki, mt * 16 + 8 + g);
            if (tg == 0) {
                float r0f, r1f, r2f, r3f;
                if (okR0) {
                    unpack2(p01a, r0f, r1f);
                    unpack2(p23a, r2f, r3f);
                    red_add_v4(acc + 4 * iR0, r0f, r1f, r2f, r3f);
                    if (PHASE == 0) red_add_f32(&g_deg[iR0], 1.0f);
                }
                if (okR1) {
                    unpack2(p01b, r0f, r1f);
                    unpack2(p23b, r2f, r3f);
                    red_add_v4(acc + 4 * iR1, r0f, r1f, r2f, r3f);
                    if (PHASE == 0) red_add_f32(&g_deg[iR1], 1.0f);
                }
            }
        }
    }
}

// ---------------- finalize encoder: mu/logvar, reparam z, decoder layer-1 precompute ----------------
__global__ void k_fin1(const float2* __restrict__ eps,
                       const float* __restrict__ mu_b, const float* __restrict__ var_b,
                       const float* __restrict__ dw1, const float* __restrict__ db1,
                       float* __restrict__ out, int n, int out_size) {
    __shared__ float sw[128];   // dec_w1 (32 x 4)
    __shared__ float sb[32];
    __shared__ float sc[4];
    int tid = threadIdx.x;
    if (tid < 128) sw[tid] = dw1[tid];
    if (tid < 32)  sb[tid] = db1[tid];
    if (tid < 2) { sc[tid] = mu_b[tid]; sc[2 + tid] = var_b[tid]; }
    __syncthreads();
    bool write_heads = (out_size >= 8 * n);
    float2* out_mu = (float2*)(out + 4 * n);
    float2* out_lv = (float2*)(out + 6 * n);
    int t = blockIdx.x * blockDim.x + tid;
    int stride = gridDim.x * blockDim.x;
    for (int i = t; i < n; i += stride) {
        float4 a = g_enc_acc[i];
        float inv = 1.0f / fmaxf(g_deg[i], 1.0f);
        float mu0 = a.x * inv + sc[0];
        float mu1 = a.y * inv + sc[1];
        float lv0 = a.z * inv + sc[2];
        float lv1 = a.w * inv + sc[3];
        float2 ep = eps[i];
        float z0 = mu0 + ep.x * expf(0.5f * lv0);
        float z1 = mu1 + ep.y * expf(0.5f * lv1);
        if (write_heads) {
            out_mu[i] = make_float2(mu0, mu1);
            out_lv[i] = make_float2(lv0, lv1);
        }
        float4 ra[8], rb[8];
        float* pa = (float*)ra;
        float* pb = (float*)rb;
#pragma unroll
        for (int k = 0; k < 32; k++) {
            const float* w = sw + k * 4;
            float b = w[2] * z0 + w[3] * z1;
            float aa = sb[k] + w[0] * z0 + w[1] * z1 - b;
            pa[k] = aa;
            pb[k] = b;
        }
#pragma unroll
        for (int q8 = 0; q8 < 8; q8++) {
            g_da[i * 8 + q8] = ra[q8];
            g_db[i * 8 + q8] = rb[q8];
        }
    }
}

// ---------------- finalize decoder output ----------------
__global__ void k_fin2(const float* __restrict__ b3, float4* __restrict__ out, int n) {
    int t = blockIdx.x * blockDim.x + threadIdx.x;
    int stride = gridDim.x * blockDim.x;
    float c0 = b3[0], c1 = b3[1], c2 = b3[2], c3 = b3[3];
    for (int i = t; i < n; i += stride) {
        float4 a = g_dec_acc[i];
        float d = g_deg[i];
        float4 o;
        if (d > 0.5f) {
            float inv = 1.0f / d;
            o = make_float4(a.x * inv + c0, a.y * inv + c1, a.z * inv + c2, a.w * inv + c3);
        } else {
            o = make_float4(0.f, 0.f, 0.f, 0.f);
        }
        out[i] = o;
    }
}

// ---------------- launch ----------------
extern "C" void kernel_launch(void* const* d_in, const int* in_sizes, int n_in,
                              void* d_out, int out_size) {
    const float* x     = (const float*)d_in[0];
    const float* eps   = (const float*)d_in[1];
    const float* gamma = (const float*)d_in[2];
    const float* beta  = (const float*)d_in[3];
    const float* ew1   = (const float*)d_in[4];
    const float* eb1   = (const float*)d_in[5];
    const float* ew2   = (const float*)d_in[6];
    const float* eb2   = (const float*)d_in[7];
    const float* muw   = (const float*)d_in[8];
    const float* mub   = (const float*)d_in[9];
    const float* vw    = (const float*)d_in[10];
    const float* vb    = (const float*)d_in[11];
    const float* dw1   = (const float*)d_in[12];
    const float* db1   = (const float*)d_in[13];
    const float* dw2   = (const float*)d_in[14];
    const float* db2   = (const float*)d_in[15];
    const float* dw3   = (const float*)d_in[16];
    const float* db3   = (const float*)d_in[17];
    const int*   ei    = (const int*)d_in[18];   // int32

    int n = in_sizes[0] / 4;
    int E = in_sizes[18] / 2;
    float* out = (float*)d_out;

    k_zero<<<256, 256>>>(n);
    k_bn_reduce<<<160, 256>>>((const float4*)x, n);
    k_prep_enc<<<256, 256>>>((const float4*)x, ew1, eb1, gamma, beta, n);

    int eblocks = 1776;   // 6 blocks/SM x 148 SMs x 2 waves over 25000 tiles
    k_edge<0><<<eblocks, 128>>>(ei, E, n, ew2, eb2, muw, vw);
    k_fin1<<<256, 256>>>((const float2*)eps, mub, vb, dw1, db1, out, n, out_size);
    k_edge<1><<<eblocks, 128>>>(ei, E, n, dw2, db2, dw3, dw3 + 64);
    k_fin2<<<128, 256>>>(db3, (float4*)out, n);
}

// round 10
// speedup vs baseline: 1.2109x; 1.2109x over previous
#include <cuda_runtime.h>
#include <cstdint>

#define MAXN 100000
typedef unsigned long long ull;

// ---------------- device scratch (static: no allocations allowed) ----------------
__device__ float  g_bn[8];              // sum[4], sumsq[4]
__device__ float  g_deg[MAXN];
__device__ float4 g_enc_acc[MAXN];      // {mu0,mu1,lv0,lv1} sums
__device__ float4 g_dec_acc[MAXN];      // {o0..o3} sums
__device__ float4 g_ea[MAXN * 8];       // A@xn + b1  (N x 32)
__device__ float4 g_eb[MAXN * 8];       // B@xn       (N x 32)
__device__ float4 g_da[MAXN * 8];       // decoder A@z + b1
__device__ float4 g_db[MAXN * 8];       // decoder B@z

__device__ __forceinline__ void red_add_v4(float* p, float a, float b, float c, float d) {
    asm volatile("red.global.add.v4.f32 [%0], {%1,%2,%3,%4};"
                 :: "l"(p), "f"(a), "f"(b), "f"(c), "f"(d) : "memory");
}
__device__ __forceinline__ void red_add_f32(float* p, float a) {
    asm volatile("red.global.add.f32 [%0], %1;" :: "l"(p), "f"(a) : "memory");
}
__device__ __forceinline__ ull pack2(float lo, float hi) {
    ull d;
    asm("mov.b64 %0, {%1, %2};" : "=l"(d) : "f"(lo), "f"(hi));
    return d;
}
__device__ __forceinline__ ull packdup(float x) {
    ull d;
    asm("mov.b64 %0, {%1, %1};" : "=l"(d) : "f"(x));
    return d;
}
__device__ __forceinline__ void unpack2(ull v, float& lo, float& hi) {
    asm("mov.b64 {%0, %1}, %2;" : "=f"(lo), "=f"(hi) : "l"(v));
}
__device__ __forceinline__ ull fma2(ull a, ull b, ull c) {
    ull d;
    asm("fma.rn.f32x2 %0, %1, %2, %3;" : "=l"(d) : "l"(a), "l"(b), "l"(c));
    return d;
}
__device__ __forceinline__ uint32_t f2tf32(float f) {
    uint32_t r;
    asm("cvt.rna.tf32.f32 %0, %1;" : "=r"(r) : "f"(f));
    return r;
}

// ---------------- zero accumulators ----------------
__global__ void k_zero(int n) {
    int t = blockIdx.x * blockDim.x + threadIdx.x;
    int stride = gridDim.x * blockDim.x;
    float4 z = make_float4(0.f, 0.f, 0.f, 0.f);
    for (int i = t; i < n; i += stride) {
        g_enc_acc[i] = z;
        g_dec_acc[i] = z;
        g_deg[i] = 0.f;
    }
    if (t < 8) g_bn[t] = 0.f;
}

// ---------------- batchnorm statistics ----------------
__global__ void k_bn_reduce(const float4* __restrict__ x, int n) {
    int t = blockIdx.x * blockDim.x + threadIdx.x;
    int stride = gridDim.x * blockDim.x;
    float s[4] = {0.f, 0.f, 0.f, 0.f};
    float q[4] = {0.f, 0.f, 0.f, 0.f};
    for (int i = t; i < n; i += stride) {
        float4 v = x[i];
        s[0] += v.x; q[0] += v.x * v.x;
        s[1] += v.y; q[1] += v.y * v.y;
        s[2] += v.z; q[2] += v.z * v.z;
        s[3] += v.w; q[3] += v.w * v.w;
    }
#pragma unroll
    for (int o = 16; o > 0; o >>= 1) {
#pragma unroll
        for (int c = 0; c < 4; c++) {
            s[c] += __shfl_down_sync(0xffffffffu, s[c], o);
            q[c] += __shfl_down_sync(0xffffffffu, q[c], o);
        }
    }
    if ((threadIdx.x & 31) == 0) {
#pragma unroll
        for (int c = 0; c < 4; c++) {
            atomicAdd(&g_bn[c], s[c]);
            atomicAdd(&g_bn[4 + c], q[c]);
        }
    }
}

// ---------------- encoder node precompute: BN + linearized layer 1 ----------------
__global__ void k_prep_enc(const float4* __restrict__ x,
                           const float* __restrict__ w1, const float* __restrict__ b1,
                           const float* __restrict__ gamma, const float* __restrict__ beta,
                           int n) {
    __shared__ float sw[256];   // enc_w1 (32 x 8) row-major
    __shared__ float sb1[32];
    __shared__ float sm[4], ss[4], sbt[4];
    int tid = threadIdx.x;
    if (tid < 256) sw[tid] = w1[tid];
    if (tid < 32)  sb1[tid] = b1[tid];
    if (tid < 4) {
        float m = g_bn[tid] / (float)n;
        float var = g_bn[4 + tid] / (float)n - m * m;
        sm[tid]  = m;
        ss[tid]  = rsqrtf(var + 1e-5f) * gamma[tid];
        sbt[tid] = beta[tid];
    }
    __syncthreads();
    int t = blockIdx.x * blockDim.x + tid;
    int stride = gridDim.x * blockDim.x;
    for (int i = t; i < n; i += stride) {
        float4 xv = x[i];
        float x0 = (xv.x - sm[0]) * ss[0] + sbt[0];
        float x1 = (xv.y - sm[1]) * ss[1] + sbt[1];
        float x2 = (xv.z - sm[2]) * ss[2] + sbt[2];
        float x3 = (xv.w - sm[3]) * ss[3] + sbt[3];
        float4 ra[8], rb[8];
        float* pa = (float*)ra;
        float* pb = (float*)rb;
#pragma unroll
        for (int k = 0; k < 32; k++) {
            const float* w = sw + k * 8;
            float b = w[4] * x0 + w[5] * x1 + w[6] * x2 + w[7] * x3;
            float a = sb1[k] + w[0] * x0 + w[1] * x1 + w[2] * x2 + w[3] * x3 - b;
            pa[k] = a;
            pb[k] = b;
        }
#pragma unroll
        for (int q8 = 0; q8 < 8; q8++) {
            g_ea[i * 8 + q8] = ra[q8];
            g_eb[i * 8 + q8] = rb[q8];
        }
    }
}

// ---------------- per-edge kernel: staged gather -> mma.sync tf32 -> project + RED ----
// Warp-tile = 64 edges (2 halves of 32). A = tf32 u rows [64x32] in warp-private smem;
// 16 gather passes (32 LDG.128) in flight per iteration for high MLP.
// B = W2 [32x32] persistent register fragments. Bias seeds MMA accumulators.
// Epilogue per 16-row sub-tile: relu, packed projection, shfl-reduce over tg, RED.
#define RS 36
template <int PHASE>
__global__ void __launch_bounds__(128, 4)
k_edge(const int* __restrict__ ei, int E, int n,
       const float* __restrict__ w2, const float* __restrict__ b2,
       const float* __restrict__ pA, const float* __restrict__ pB) {
    __shared__ __align__(16) float su[4 * 64 * RS];   // 36.9KB
    __shared__ ull s_pc01[32], s_pc23[32];   // {pA[c],pA[32+c]}, {pB[c],pB[32+c]}
    __shared__ float s_b2[32];
    int tid = threadIdx.x;
    int warp = tid >> 5, lane = tid & 31;
    int g = lane >> 2, tg = lane & 3;

    if (tid < 32) {
        s_pc01[tid] = pack2(pA[tid], pA[32 + tid]);
        s_pc23[tid] = pack2(pB[tid], pB[32 + tid]);
        s_b2[tid] = b2[tid];
    }

    // Persistent B fragments: bf0/bf1[nt][kt] = w2[8nt+g][8kt+tg(+4)]
    uint32_t bf0[4][4], bf1[4][4];
#pragma unroll
    for (int nt = 0; nt < 4; nt++)
#pragma unroll
        for (int kt = 0; kt < 4; kt++) {
            bf0[nt][kt] = f2tf32(w2[(8 * nt + g) * 32 + 8 * kt + tg]);
            bf1[nt][kt] = f2tf32(w2[(8 * nt + g) * 32 + 8 * kt + tg + 4]);
        }
    __syncthreads();

    const float4* fa = (PHASE == 0) ? g_ea : g_da;
    const float4* fb = (PHASE == 0) ? g_eb : g_db;
    float* acc = (PHASE == 0) ? (float*)g_enc_acc : (float*)g_dec_acc;

    float* stage = su + warp * 64 * RS;
    int c8 = lane & 7, rsub = lane >> 3;
    int ntiles = (E + 255) >> 8;   // 256 edges per block-tile (64 per warp)
    const ull ONE = packdup(1.0f);

    for (int t = blockIdx.x; t < ntiles; t += gridDim.x) {
        int base = (t << 8) + (warp << 6);
        int eA = base + lane;
        int eB = base + 32 + lane;
        bool okA = (eA < E), okB = (eB < E);
        int eAc = okA ? eA : (E - 1);
        int eBc = okB ? eB : (E - 1);
        unsigned jA = (unsigned)ei[eAc];
        unsigned iA = (unsigned)ei[E + eAc];
        unsigned jB = (unsigned)ei[eBc];
        unsigned iB = (unsigned)ei[E + eBc];
        okA = okA && (jA < (unsigned)n) && (iA < (unsigned)n);
        okB = okB && (jB < (unsigned)n) && (iB < (unsigned)n);
        unsigned jsA = okA ? jA : 0u, isA = okA ? iA : 0u;
        unsigned jsB = okB ? jB : 0u, isB = okB ? iB : 0u;
        unsigned okiA = okA ? 1u : 0u, okiB = okB ? 1u : 0u;

        __syncwarp();   // stage is warp-private; prior iter reads done
#pragma unroll
        for (int h = 0; h < 2; h++) {
#pragma unroll
            for (int gg = 0; gg < 8; gg++) {
                int er = 4 * gg + rsub;
                unsigned nd = __shfl_sync(0xffffffffu, h ? isB : isA, er);
                unsigned ns = __shfl_sync(0xffffffffu, h ? jsB : jsA, er);
                float4 a = fa[nd * 8 + c8];
                float4 b = fb[ns * 8 + c8];
                uint4 u;   // tf32 bit patterns (cvt overlaps gather latency)
                u.x = f2tf32(fmaxf(a.x + b.x, 0.f));
                u.y = f2tf32(fmaxf(a.y + b.y, 0.f));
                u.z = f2tf32(fmaxf(a.z + b.z, 0.f));
                u.w = f2tf32(fmaxf(a.w + b.w, 0.f));
                *(uint4*)(stage + (h * 32 + er) * RS + c8 * 4) = u;
            }
        }
        __syncwarp();

#pragma unroll
        for (int mt = 0; mt < 4; mt++) {
            float c[4][4];
#pragma unroll
            for (int nt = 0; nt < 4; nt++) {
                float bb0 = s_b2[8 * nt + 2 * tg];
                float bb1 = s_b2[8 * nt + 2 * tg + 1];
                c[nt][0] = bb0; c[nt][1] = bb1;
                c[nt][2] = bb0; c[nt][3] = bb1;
            }

#pragma unroll
            for (int kt = 0; kt < 4; kt++) {
                const float* ab = stage + (mt * 16 + g) * RS + kt * 8 + tg;
                uint32_t a0 = __float_as_uint(ab[0]);
                uint32_t a1 = __float_as_uint(ab[8 * RS]);
                uint32_t a2 = __float_as_uint(ab[4]);
                uint32_t a3 = __float_as_uint(ab[8 * RS + 4]);
#pragma unroll
                for (int nt = 0; nt < 4; nt++) {
                    asm volatile(
                        "mma.sync.aligned.m16n8k8.row.col.f32.tf32.tf32.f32 "
                        "{%0,%1,%2,%3}, {%4,%5,%6,%7}, {%8,%9}, {%0,%1,%2,%3};"
                        : "+f"(c[nt][0]), "+f"(c[nt][1]), "+f"(c[nt][2]), "+f"(c[nt][3])
                        : "r"(a0), "r"(a1), "r"(a2), "r"(a3),
                          "r"(bf0[nt][kt]), "r"(bf1[nt][kt]));
                }
            }

            // epilogue: rows r0 = mt*16+g, r1 = mt*16+8+g (halves: mt<2 -> A, mt>=2 -> B)
            ull p01a = 0, p23a = 0, p01b = 0, p23b = 0;
#pragma unroll
            for (int nt = 0; nt < 4; nt++) {
                int c0i = 8 * nt + 2 * tg;
                ull q0 = s_pc01[c0i], q1 = s_pc01[c0i + 1];
                ull q2 = s_pc23[c0i], q3 = s_pc23[c0i + 1];
                float r0 = fmaxf(c[nt][0], 0.f);
                float r1 = fmaxf(c[nt][1], 0.f);
                float r2 = fmaxf(c[nt][2], 0.f);
                float r3 = fmaxf(c[nt][3], 0.f);
                p01a = fma2(q0, packdup(r0), p01a);
                p23a = fma2(q2, packdup(r0), p23a);
                p01a = fma2(q1, packdup(r1), p01a);
                p23a = fma2(q3, packdup(r1), p23a);
                p01b = fma2(q0, packdup(r2), p01b);
                p23b = fma2(q2, packdup(r2), p23b);
                p01b = fma2(q1, packdup(r3), p01b);
                p23b = fma2(q3, packdup(r3), p23b);
            }
#pragma unroll
            for (int m = 1; m <= 2; m <<= 1) {
                p01a = fma2(ONE, __shfl_xor_sync(0xffffffffu, p01a, m), p01a);
                p23a = fma2(ONE, __shfl_xor_sync(0xffffffffu, p23a, m), p23a);
                p01b = fma2(ONE, __shfl_xor_sync(0xffffffffu, p01b, m), p01b);
                p23b = fma2(ONE, __shfl_xor_sync(0xffffffffu, p23b, m), p23b);
            }
            unsigned isH  = (mt < 2) ? isA : isB;
            unsigned okiH = (mt < 2) ? okiA : okiB;
            int rh = (mt & 1) * 16 + g;   // row within half
            unsigned iR0  = __shfl_sync(0xffffffffu, isH,  rh);
            unsigned okR0 = __shfl_sync(0xffffffffu, okiH, rh);
            unsigned iR1  = __shfl_sync(0xffffffffu, isH,  rh + 8);
            unsigned okR1 = __shfl_sync(0xffffffffu, okiH, rh + 8);
            if (tg == 0) {
                float r0, r1, r2, r3;
                if (okR0) {
                    unpack2(p01a, r0, r1);
                    unpack2(p23a, r2, r3);
                    red_add_v4(acc + 4 * iR0, r0, r1, r2, r3);
                    if (PHASE == 0) red_add_f32(&g_deg[iR0], 1.0f);
                }
                if (okR1) {
                    unpack2(p01b, r0, r1);
                    unpack2(p23b, r2, r3);
                    red_add_v4(acc + 4 * iR1, r0, r1, r2, r3);
                    if (PHASE == 0) red_add_f32(&g_deg[iR1], 1.0f);
                }
            }
        }
    }
}

// ---------------- finalize encoder: mu/logvar, reparam z, decoder layer-1 precompute ----------------
__global__ void k_fin1(const float2* __restrict__ eps,
                       const float* __restrict__ mu_b, const float* __restrict__ var_b,
                       const float* __restrict__ dw1, const float* __restrict__ db1,
                       float* __restrict__ out, int n, int out_size) {
    __shared__ float sw[128];   // dec_w1 (32 x 4)
    __shared__ float sb[32];
    __shared__ float sc[4];
    int tid = threadIdx.x;
    if (tid < 128) sw[tid] = dw1[tid];
    if (tid < 32)  sb[tid] = db1[tid];
    if (tid < 2) { sc[tid] = mu_b[tid]; sc[2 + tid] = var_b[tid]; }
    __syncthreads();
    bool write_heads = (out_size >= 8 * n);
    float2* out_mu = (float2*)(out + 4 * n);
    float2* out_lv = (float2*)(out + 6 * n);
    int t = blockIdx.x * blockDim.x + tid;
    int stride = gridDim.x * blockDim.x;
    for (int i = t; i < n; i += stride) {
        float4 a = g_enc_acc[i];
        float inv = 1.0f / fmaxf(g_deg[i], 1.0f);
        float mu0 = a.x * inv + sc[0];
        float mu1 = a.y * inv + sc[1];
        float lv0 = a.z * inv + sc[2];
        float lv1 = a.w * inv + sc[3];
        float2 ep = eps[i];
        float z0 = mu0 + ep.x * expf(0.5f * lv0);
        float z1 = mu1 + ep.y * expf(0.5f * lv1);
        if (write_heads) {
            out_mu[i] = make_float2(mu0, mu1);
            out_lv[i] = make_float2(lv0, lv1);
        }
        float4 ra[8], rb[8];
        float* pa = (float*)ra;
        float* pb = (float*)rb;
#pragma unroll
        for (int k = 0; k < 32; k++) {
            const float* w = sw + k * 4;
            float b = w[2] * z0 + w[3] * z1;
            float aa = sb[k] + w[0] * z0 + w[1] * z1 - b;
            pa[k] = aa;
            pb[k] = b;
        }
#pragma unroll
        for (int q8 = 0; q8 < 8; q8++) {
            g_da[i * 8 + q8] = ra[q8];
            g_db[i * 8 + q8] = rb[q8];
        }
    }
}

// ---------------- finalize decoder output ----------------
__global__ void k_fin2(const float* __restrict__ b3, float4* __restrict__ out, int n) {
    int t = blockIdx.x * blockDim.x + threadIdx.x;
    int stride = gridDim.x * blockDim.x;
    float c0 = b3[0], c1 = b3[1], c2 = b3[2], c3 = b3[3];
    for (int i = t; i < n; i += stride) {
        float4 a = g_dec_acc[i];
        float d = g_deg[i];
        float4 o;
        if (d > 0.5f) {
            float inv = 1.0f / d;
            o = make_float4(a.x * inv + c0, a.y * inv + c1, a.z * inv + c2, a.w * inv + c3);
        } else {
            o = make_float4(0.f, 0.f, 0.f, 0.f);
        }
        out[i] = o;
    }
}

// ---------------- launch ----------------
extern "C" void kernel_launch(void* const* d_in, const int* in_sizes, int n_in,
                              void* d_out, int out_size) {
    const float* x     = (const float*)d_in[0];
    const float* eps   = (const float*)d_in[1];
    const float* gamma = (const float*)d_in[2];
    const float* beta  = (const float*)d_in[3];
    const float* ew1   = (const float*)d_in[4];
    const float* eb1   = (const float*)d_in[5];
    const float* ew2   = (const float*)d_in[6];
    const float* eb2   = (const float*)d_in[7];
    const float* muw   = (const float*)d_in[8];
    const float* mub   = (const float*)d_in[9];
    const float* vw    = (const float*)d_in[10];
    const float* vb    = (const float*)d_in[11];
    const float* dw1   = (const float*)d_in[12];
    const float* db1   = (const float*)d_in[13];
    const float* dw2   = (const float*)d_in[14];
    const float* db2   = (const float*)d_in[15];
    const float* dw3   = (const float*)d_in[16];
    const float* db3   = (const float*)d_in[17];
    const int*   ei    = (const int*)d_in[18];   // int32

    int n = in_sizes[0] / 4;
    int E = in_sizes[18] / 2;
    float* out = (float*)d_out;

    k_zero<<<256, 256>>>(n);
    k_bn_reduce<<<160, 256>>>((const float4*)x, n);
    k_prep_enc<<<256, 256>>>((const float4*)x, ew1, eb1, gamma, beta, n);

    int eblocks = 1184;   // grid-stride over 12500 tiles of 256 edges
    k_edge<0><<<eblocks, 128>>>(ei, E, n, ew2, eb2, muw, vw);
    k_fin1<<<256, 256>>>((const float2*)eps, mub, vb, dw1, db1, out, n, out_size);
    k_edge<1><<<eblocks, 128>>>(ei, E, n, dw2, db2, dw3, dw3 + 64);
    k_fin2<<<128, 256>>>(db3, (float4*)out, n);
}

// round 11
// speedup vs baseline: 1.3332x; 1.1010x over previous
#include <cuda_runtime.h>
#include <cstdint>

#define MAXN 100000
typedef unsigned long long ull;

// ---------------- device scratch (static: no allocations allowed) ----------------
__device__ float  g_bn[8];              // sum[4], sumsq[4]
__device__ float  g_deg[MAXN];
__device__ float4 g_enc_acc[MAXN];      // {mu0,mu1,lv0,lv1} sums
__device__ float4 g_dec_acc[MAXN];      // {o0..o3} sums
__device__ float4 g_ea[MAXN * 8];       // A@xn + b1  (N x 32)
__device__ float4 g_eb[MAXN * 8];       // B@xn       (N x 32)
__device__ float4 g_da[MAXN * 8];       // decoder A@z + b1
__device__ float4 g_db[MAXN * 8];       // decoder B@z

__device__ __forceinline__ void red_add_v4(float* p, float a, float b, float c, float d) {
    asm volatile("red.global.add.v4.f32 [%0], {%1,%2,%3,%4};"
                 :: "l"(p), "f"(a), "f"(b), "f"(c), "f"(d) : "memory");
}
__device__ __forceinline__ void red_add_f32(float* p, float a) {
    asm volatile("red.global.add.f32 [%0], %1;" :: "l"(p), "f"(a) : "memory");
}
__device__ __forceinline__ ull pack2(float lo, float hi) {
    ull d;
    asm("mov.b64 %0, {%1, %2};" : "=l"(d) : "f"(lo), "f"(hi));
    return d;
}
__device__ __forceinline__ void unpack2(ull v, float& lo, float& hi) {
    asm("mov.b64 {%0, %1}, %2;" : "=f"(lo), "=f"(hi) : "l"(v));
}
__device__ __forceinline__ uint32_t f2tf32(float f) {
    uint32_t r;
    asm("cvt.rna.tf32.f32 %0, %1;" : "=r"(r) : "f"(f));
    return r;
}
// pack two f32 to f16x2: hi -> high half, lo -> low half
__device__ __forceinline__ uint32_t cvt_h2(float hi, float lo) {
    uint32_t r;
    asm("cvt.rn.f16x2.f32 %0, %1, %2;" : "=r"(r) : "f"(hi), "f"(lo));
    return r;
}

// ---------------- zero accumulators ----------------
__global__ void k_zero(int n) {
    int t = blockIdx.x * blockDim.x + threadIdx.x;
    int stride = gridDim.x * blockDim.x;
    float4 z = make_float4(0.f, 0.f, 0.f, 0.f);
    for (int i = t; i < n; i += stride) {
        g_enc_acc[i] = z;
        g_dec_acc[i] = z;
        g_deg[i] = 0.f;
    }
    if (t < 8) g_bn[t] = 0.f;
}

// ---------------- batchnorm statistics ----------------
__global__ void k_bn_reduce(const float4* __restrict__ x, int n) {
    int t = blockIdx.x * blockDim.x + threadIdx.x;
    int stride = gridDim.x * blockDim.x;
    float s[4] = {0.f, 0.f, 0.f, 0.f};
    float q[4] = {0.f, 0.f, 0.f, 0.f};
    for (int i = t; i < n; i += stride) {
        float4 v = x[i];
        s[0] += v.x; q[0] += v.x * v.x;
        s[1] += v.y; q[1] += v.y * v.y;
        s[2] += v.z; q[2] += v.z * v.z;
        s[3] += v.w; q[3] += v.w * v.w;
    }
#pragma unroll
    for (int o = 16; o > 0; o >>= 1) {
#pragma unroll
        for (int c = 0; c < 4; c++) {
            s[c] += __shfl_down_sync(0xffffffffu, s[c], o);
            q[c] += __shfl_down_sync(0xffffffffu, q[c], o);
        }
    }
    if ((threadIdx.x & 31) == 0) {
#pragma unroll
        for (int c = 0; c < 4; c++) {
            atomicAdd(&g_bn[c], s[c]);
            atomicAdd(&g_bn[4 + c], q[c]);
        }
    }
}

// ---------------- encoder node precompute: BN + linearized layer 1 ----------------
__global__ void k_prep_enc(const float4* __restrict__ x,
                           const float* __restrict__ w1, const float* __restrict__ b1,
                           const float* __restrict__ gamma, const float* __restrict__ beta,
                           int n) {
    __shared__ float sw[256];   // enc_w1 (32 x 8) row-major
    __shared__ float sb1[32];
    __shared__ float sm[4], ss[4], sbt[4];
    int tid = threadIdx.x;
    if (tid < 256) sw[tid] = w1[tid];
    if (tid < 32)  sb1[tid] = b1[tid];
    if (tid < 4) {
        float m = g_bn[tid] / (float)n;
        float var = g_bn[4 + tid] / (float)n - m * m;
        sm[tid]  = m;
        ss[tid]  = rsqrtf(var + 1e-5f) * gamma[tid];
        sbt[tid] = beta[tid];
    }
    __syncthreads();
    int t = blockIdx.x * blockDim.x + tid;
    int stride = gridDim.x * blockDim.x;
    for (int i = t; i < n; i += stride) {
        float4 xv = x[i];
        float x0 = (xv.x - sm[0]) * ss[0] + sbt[0];
        float x1 = (xv.y - sm[1]) * ss[1] + sbt[1];
        float x2 = (xv.z - sm[2]) * ss[2] + sbt[2];
        float x3 = (xv.w - sm[3]) * ss[3] + sbt[3];
        float4 ra[8], rb[8];
        float* pa = (float*)ra;
        float* pb = (float*)rb;
#pragma unroll
        for (int k = 0; k < 32; k++) {
            const float* w = sw + k * 8;
            float b = w[4] * x0 + w[5] * x1 + w[6] * x2 + w[7] * x3;
            float a = sb1[k] + w[0] * x0 + w[1] * x1 + w[2] * x2 + w[3] * x3 - b;
            pa[k] = a;
            pb[k] = b;
        }
#pragma unroll
        for (int q8 = 0; q8 < 8; q8++) {
            g_ea[i * 8 + q8] = ra[q8];
            g_eb[i * 8 + q8] = rb[q8];
        }
    }
}

// ---------------- per-edge kernel: staged gather -> tf32 MMA -> chained f16 MMA -> RED ----
// Warp-tile = 64 edges. A = tf32 u rows [64x32] in warp-private smem (32 LDG.128/iter MLP).
// GEMM1: W2 [32x32] persistent tf32 B-frags, bias-seeded accumulators.
// GEMM2 (projection): relu(C1) in-lane cvt to f16 A-frags (flash-attn chaining),
// P [32x8] (cols 0-3 = proj rows, 4-7 zero) persistent f16 B-frags -> D has outputs
// in lanes tg=0 (mu01) / tg=1 (lv01); one 64-bit shfl pairs them; RED v4 + deg.
#define RS 36
template <int PHASE>
__global__ void __launch_bounds__(128, 4)
k_edge(const int* __restrict__ ei, int E, int n,
       const float* __restrict__ w2, const float* __restrict__ b2,
       const float* __restrict__ pA, const float* __restrict__ pB) {
    __shared__ __align__(16) float su[4 * 64 * RS];   // 36.9KB
    __shared__ float s_b2[32];
    int tid = threadIdx.x;
    int warp = tid >> 5, lane = tid & 31;
    int g = lane >> 2, tg = lane & 3;

    if (tid < 32) s_b2[tid] = b2[tid];

    // GEMM1 persistent B fragments: bf0/bf1[nt][kt] = w2[8nt+g][8kt+tg(+4)]
    uint32_t bf0[4][4], bf1[4][4];
#pragma unroll
    for (int nt = 0; nt < 4; nt++)
#pragma unroll
        for (int kt = 0; kt < 4; kt++) {
            bf0[nt][kt] = f2tf32(w2[(8 * nt + g) * 32 + 8 * kt + tg]);
            bf1[nt][kt] = f2tf32(w2[(8 * nt + g) * 32 + 8 * kt + tg + 4]);
        }

    // GEMM2 persistent B fragments: P[k][n], n = g (cols 0-3 real, 4-7 zero)
    // P[k][0]=pA[k], [1]=pA[32+k], [2]=pB[k], [3]=pB[32+k]
    auto Pv = [&](int k) -> float {
        return (g == 0) ? pA[k] : (g == 1) ? pA[32 + k]
             : (g == 2) ? pB[k] : (g == 3) ? pB[32 + k] : 0.f;
    };
    uint32_t pb0[2], pb1[2];   // [m]: MMA#m; b0 = {k=2tg(+16m), 2tg+1}, b1 = {k=2tg+8(+16m),+9}
#pragma unroll
    for (int m = 0; m < 2; m++) {
        int k0 = 16 * m + 2 * tg;
        pb0[m] = cvt_h2(Pv(k0 + 1), Pv(k0));
        pb1[m] = cvt_h2(Pv(k0 + 9), Pv(k0 + 8));
    }
    __syncthreads();

    const float4* fa = (PHASE == 0) ? g_ea : g_da;
    const float4* fb = (PHASE == 0) ? g_eb : g_db;
    float* acc = (PHASE == 0) ? (float*)g_enc_acc : (float*)g_dec_acc;

    float* stage = su + warp * 64 * RS;
    int c8 = lane & 7, rsub = lane >> 3;
    int ntiles = (E + 255) >> 8;   // 256 edges per block-tile (64 per warp)

    for (int t = blockIdx.x; t < ntiles; t += gridDim.x) {
        int base = (t << 8) + (warp << 6);
        int eA = base + lane;
        int eB = base + 32 + lane;
        bool okA = (eA < E), okB = (eB < E);
        int eAc = okA ? eA : (E - 1);
        int eBc = okB ? eB : (E - 1);
        unsigned jA = (unsigned)ei[eAc];
        unsigned iA = (unsigned)ei[E + eAc];
        unsigned jB = (unsigned)ei[eBc];
        unsigned iB = (unsigned)ei[E + eBc];
        okA = okA && (jA < (unsigned)n) && (iA < (unsigned)n);
        okB = okB && (jB < (unsigned)n) && (iB < (unsigned)n);
        unsigned jsA = okA ? jA : 0u, isA = okA ? iA : 0u;
        unsigned jsB = okB ? jB : 0u, isB = okB ? iB : 0u;
        unsigned okiA = okA ? 1u : 0u, okiB = okB ? 1u : 0u;

        __syncwarp();   // stage is warp-private; prior iter reads done
#pragma unroll
        for (int h = 0; h < 2; h++) {
#pragma unroll
            for (int gg = 0; gg < 8; gg++) {
                int er = 4 * gg + rsub;
                unsigned nd = __shfl_sync(0xffffffffu, h ? isB : isA, er);
                unsigned ns = __shfl_sync(0xffffffffu, h ? jsB : jsA, er);
                float4 a = fa[nd * 8 + c8];
                float4 b = fb[ns * 8 + c8];
                uint4 u;   // tf32 bit patterns (cvt overlaps gather latency)
                u.x = f2tf32(fmaxf(a.x + b.x, 0.f));
                u.y = f2tf32(fmaxf(a.y + b.y, 0.f));
                u.z = f2tf32(fmaxf(a.z + b.z, 0.f));
                u.w = f2tf32(fmaxf(a.w + b.w, 0.f));
                *(uint4*)(stage + (h * 32 + er) * RS + c8 * 4) = u;
            }
        }
        __syncwarp();

#pragma unroll
        for (int mt = 0; mt < 4; mt++) {
            // ---- GEMM1: v = W2 @ u + b2 (bias-seeded) ----
            float c[4][4];
#pragma unroll
            for (int nt = 0; nt < 4; nt++) {
                float bb0 = s_b2[8 * nt + 2 * tg];
                float bb1 = s_b2[8 * nt + 2 * tg + 1];
                c[nt][0] = bb0; c[nt][1] = bb1;
                c[nt][2] = bb0; c[nt][3] = bb1;
            }
#pragma unroll
            for (int kt = 0; kt < 4; kt++) {
                const float* ab = stage + (mt * 16 + g) * RS + kt * 8 + tg;
                uint32_t a0 = __float_as_uint(ab[0]);
                uint32_t a1 = __float_as_uint(ab[8 * RS]);
                uint32_t a2 = __float_as_uint(ab[4]);
                uint32_t a3 = __float_as_uint(ab[8 * RS + 4]);
#pragma unroll
                for (int nt = 0; nt < 4; nt++) {
                    asm volatile(
                        "mma.sync.aligned.m16n8k8.row.col.f32.tf32.tf32.f32 "
                        "{%0,%1,%2,%3}, {%4,%5,%6,%7}, {%8,%9}, {%0,%1,%2,%3};"
                        : "+f"(c[nt][0]), "+f"(c[nt][1]), "+f"(c[nt][2]), "+f"(c[nt][3])
                        : "r"(a0), "r"(a1), "r"(a2), "r"(a3),
                          "r"(bf0[nt][kt]), "r"(bf1[nt][kt]));
                }
            }

            // ---- GEMM2: p = relu(v) @ P  (chained fp16, in-lane A-frags) ----
            float d[4] = {0.f, 0.f, 0.f, 0.f};
#pragma unroll
            for (int m = 0; m < 2; m++) {
                int n0 = 2 * m, n1 = 2 * m + 1;   // nt pair covering k = 16m..16m+15
                uint32_t a0 = cvt_h2(fmaxf(c[n0][1], 0.f), fmaxf(c[n0][0], 0.f));
                uint32_t a1 = cvt_h2(fmaxf(c[n0][3], 0.f), fmaxf(c[n0][2], 0.f));
                uint32_t a2 = cvt_h2(fmaxf(c[n1][1], 0.f), fmaxf(c[n1][0], 0.f));
                uint32_t a3 = cvt_h2(fmaxf(c[n1][3], 0.f), fmaxf(c[n1][2], 0.f));
                asm volatile(
                    "mma.sync.aligned.m16n8k16.row.col.f32.f16.f16.f32 "
                    "{%0,%1,%2,%3}, {%4,%5,%6,%7}, {%8,%9}, {%0,%1,%2,%3};"
                    : "+f"(d[0]), "+f"(d[1]), "+f"(d[2]), "+f"(d[3])
                    : "r"(a0), "r"(a1), "r"(a2), "r"(a3),
                      "r"(pb0[m]), "r"(pb1[m]));
            }

            // ---- epilogue: D rows g (d0,d1), g+8 (d2,d3); tg0 = mu01, tg1 = lv01 ----
            ull pk0 = pack2(d[0], d[1]);
            ull pk1 = pack2(d[2], d[3]);
            ull o0 = __shfl_xor_sync(0xffffffffu, pk0, 1);   // tg0 <- tg1's pair
            ull o1 = __shfl_xor_sync(0xffffffffu, pk1, 1);

            unsigned isH  = (mt < 2) ? isA : isB;
            unsigned okiH = (mt < 2) ? okiA : okiB;
            int rh = (mt & 1) * 16 + g;   // row within half
            unsigned iR0  = __shfl_sync(0xffffffffu, isH,  rh);
            unsigned okR0 = __shfl_sync(0xffffffffu, okiH, rh);
            unsigned iR1  = __shfl_sync(0xffffffffu, isH,  rh + 8);
            unsigned okR1 = __shfl_sync(0xffffffffu, okiH, rh + 8);
            if (tg == 0) {
                float m0, m1, l0, l1;
                if (okR0) {
                    unpack2(pk0, m0, m1);
                    unpack2(o0, l0, l1);
                    red_add_v4(acc + 4 * iR0, m0, m1, l0, l1);
                }
                if (okR1) {
                    unpack2(pk1, m0, m1);
                    unpack2(o1, l0, l1);
                    red_add_v4(acc + 4 * iR1, m0, m1, l0, l1);
                }
            } else if (PHASE == 0 && tg == 1) {
                if (okR0) red_add_f32(&g_deg[iR0], 1.0f);
                if (okR1) red_add_f32(&g_deg[iR1], 1.0f);
            }
        }
    }
}

// ---------------- finalize encoder: mu/logvar, reparam z, decoder layer-1 precompute ----------------
__global__ void k_fin1(const float2* __restrict__ eps,
                       const float* __restrict__ mu_b, const float* __restrict__ var_b,
                       const float* __restrict__ dw1, const float* __restrict__ db1,
                       float* __restrict__ out, int n, int out_size) {
    __shared__ float sw[128];   // dec_w1 (32 x 4)
    __shared__ float sb[32];
    __shared__ float sc[4];
    int tid = threadIdx.x;
    if (tid < 128) sw[tid] = dw1[tid];
    if (tid < 32)  sb[tid] = db1[tid];
    if (tid < 2) { sc[tid] = mu_b[tid]; sc[2 + tid] = var_b[tid]; }
    __syncthreads();
    bool write_heads = (out_size >= 8 * n);
    float2* out_mu = (float2*)(out + 4 * n);
    float2* out_lv = (float2*)(out + 6 * n);
    int t = blockIdx.x * blockDim.x + tid;
    int stride = gridDim.x * blockDim.x;
    for (int i = t; i < n; i += stride) {
        float4 a = g_enc_acc[i];
        float inv = 1.0f / fmaxf(g_deg[i], 1.0f);
        float mu0 = a.x * inv + sc[0];
        float mu1 = a.y * inv + sc[1];
        float lv0 = a.z * inv + sc[2];
        float lv1 = a.w * inv + sc[3];
        float2 ep = eps[i];
        float z0 = mu0 + ep.x * expf(0.5f * lv0);
        float z1 = mu1 + ep.y * expf(0.5f * lv1);
        if (write_heads) {
            out_mu[i] = make_float2(mu0, mu1);
            out_lv[i] = make_float2(lv0, lv1);
        }
        float4 ra[8], rb[8];
        float* pa = (float*)ra;
        float* pb = (float*)rb;
#pragma unroll
        for (int k = 0; k < 32; k++) {
            const float* w = sw + k * 4;
            float b = w[2] * z0 + w[3] * z1;
            float aa = sb[k] + w[0] * z0 + w[1] * z1 - b;
            pa[k] = aa;
            pb[k] = b;
        }
#pragma unroll
        for (int q8 = 0; q8 < 8; q8++) {
            g_da[i * 8 + q8] = ra[q8];
            g_db[i * 8 + q8] = rb[q8];
        }
    }
}

// ---------------- finalize decoder output ----------------
__global__ void k_fin2(const float* __restrict__ b3, float4* __restrict__ out, int n) {
    int t = blockIdx.x * blockDim.x + threadIdx.x;
    int stride = gridDim.x * blockDim.x;
    float c0 = b3[0], c1 = b3[1], c2 = b3[2], c3 = b3[3];
    for (int i = t; i < n; i += stride) {
        float4 a = g_dec_acc[i];
        float d = g_deg[i];
        float4 o;
        if (d > 0.5f) {
            float inv = 1.0f / d;
            o = make_float4(a.x * inv + c0, a.y * inv + c1, a.z * inv + c2, a.w * inv + c3);
        } else {
            o = make_float4(0.f, 0.f, 0.f, 0.f);
        }
        out[i] = o;
    }
}

// ---------------- launch ----------------
extern "C" void kernel_launch(void* const* d_in, const int* in_sizes, int n_in,
                              void* d_out, int out_size) {
    const float* x     = (const float*)d_in[0];
    const float* eps   = (const float*)d_in[1];
    const float* gamma = (const float*)d_in[2];
    const float* beta  = (const float*)d_in[3];
    const float* ew1   = (const float*)d_in[4];
    const float* eb1   = (const float*)d_in[5];
    const float* ew2   = (const float*)d_in[6];
    const float* eb2   = (const float*)d_in[7];
    const float* muw   = (const float*)d_in[8];
    const float* mub   = (const float*)d_in[9];
    const float* vw    = (const float*)d_in[10];
    const float* vb    = (const float*)d_in[11];
    const float* dw1   = (const float*)d_in[12];
    const float* db1   = (const float*)d_in[13];
    const float* dw2   = (const float*)d_in[14];
    const float* db2   = (const float*)d_in[15];
    const float* dw3   = (const float*)d_in[16];
    const float* db3   = (const float*)d_in[17];
    const int*   ei    = (const int*)d_in[18];   // int32

    int n = in_sizes[0] / 4;
    int E = in_sizes[18] / 2;
    float* out = (float*)d_out;

    k_zero<<<256, 256>>>(n);
    k_bn_reduce<<<160, 256>>>((const float4*)x, n);
    k_prep_enc<<<256, 256>>>((const float4*)x, ew1, eb1, gamma, beta, n);

    int eblocks = 1184;   // grid-stride over 12500 tiles of 256 edges
    k_edge<0><<<eblocks, 128>>>(ei, E, n, ew2, eb2, muw, vw);
    k_fin1<<<256, 256>>>((const float2*)eps, mub, vb, dw1, db1, out, n, out_size);
    k_edge<1><<<eblocks, 128>>>(ei, E, n, dw2, db2, dw3, dw3 + 64);
    k_fin2<<<128, 256>>>(db3, (float4*)out, n);
}